// round 12
// baseline (speedup 1.0000x reference)
#include <cuda_runtime.h>
#include <cuda_bf16.h>
#include <cstdint>

// Problem constants
constexpr int Bc  = 2;
constexpr int Nc  = 50;
constexpr int NG  = 15;
constexpr int Cc  = 17;
constexpr int HWc = 4096;

constexpr int KCHUNK = 512;
constexpr int KIN    = 64;
constexpr int NIT    = KCHUNK / KIN;   // 8
constexpr int IL     = 32;             // pred rows per CTA (i-half)
constexpr int JPAD   = 16;
constexpr int THREADS = 256;           // 8 warps
constexpr int XB     = HWc / KCHUNK;   // 8 k-blocks

// one smem buffer: A,B,C [IL][KIN], U,V,W [JPAD][KIN]
constexpr int OFF_A = 0;
constexpr int OFF_B = OFF_A + IL * KIN;
constexpr int OFF_C = OFF_B + IL * KIN;
constexpr int OFF_U = OFF_C + IL * KIN;
constexpr int OFF_V = OFF_U + JPAD * KIN;
constexpr int OFF_W = OFF_V + JPAD * KIN;
constexpr int HALF  = OFF_W + JPAD * KIN;                 // 9216 floats
constexpr size_t SMEM_BYTES = 2 * HALF * sizeof(float);   // 72 KB

// Partial accumulators: each slot written by exactly one CTA. No init, no atomics.
__device__ __align__(16) float g_accp[Bc * Nc * NG * Cc * XB];
__device__ __align__(16) float g_sap [Bc * Nc * Cc * XB];
__device__ __align__(16) int   g_maskp[Bc * NG * Cc * XB];

#define FMA_F32X2(d, a, b, c) \
    asm("fma.rn.f32x2 %0, %1, %2, %3;" : "=l"(d) : "l"(a), "l"(b), "l"(c))

// ---------------------------------------------------------------------------
// Kernel 1: fused transform + 3-term GEMM + mask partials.
// grid (XB*2, Cc, Bc) = 544 CTAs, block 256 (8 warps), 2 CTAs/SM resident.
// blockIdx.x: xb = x>>1 (k-chunk), ih = x&1 (i-half: rows ih*32..ih*32+31).
// warp w: local i rows [4w,4w+4); lanes 0-15 -> j 0..7, 16-31 -> j 8..15.
// ---------------------------------------------------------------------------
__global__ __launch_bounds__(THREADS, 2)
void gemm_kernel(const float* __restrict__ ph, const float* __restrict__ gh) {
    extern __shared__ float sm[];

    const int x  = blockIdx.x, c = blockIdx.y, b = blockIdx.z;
    const int xb = x >> 1, ih = x & 1;
    const int k0 = xb * KCHUNK;

    const int tid  = threadIdx.x;
    const int lane = tid & 31;
    const int wrp  = tid >> 5;           // 0..7
    const int lk   = lane & 15;
    const int half = lane >> 4;
    const int i_loc  = wrp * 4;          // local i base
    const int j_base = half * 8;

    // zero invalid pred pad rows once (ih=1: local rows 18..31 = global 50..63)
    if (ih == 1) {
        for (int idx = tid; idx < (IL - (Nc - IL)) * KIN; idx += THREADS) {
#pragma unroll
            for (int bu = 0; bu < 2; bu++) {
                sm[bu * HALF + OFF_A + (Nc - IL) * KIN + idx] = 0.f;
                sm[bu * HALF + OFF_B + (Nc - IL) * KIN + idx] = 0.f;
                sm[bu * HALF + OFF_C + (Nc - IL) * KIN + idx] = 0.f;
            }
        }
    }

    const float* phb = ph + ((size_t)(b * Nc * Cc + c)) * HWc;
    const float* ghb = gh + ((size_t)(b * NG * Cc + c)) * HWc;

    // staging coords: pred items idx = tid, tid+256 over [IL][16] float4s
    const int pr0 = tid >> 4;            // local row 0..15
    const int pr1 = pr0 + 16;            // local row 16..31
    const int pc0 = (tid & 15) << 2;
    const int gi0 = ih * IL + pr0;       // global pred row (always < Nc)
    const int gi1 = ih * IL + pr1;       // may be >= Nc for ih=1
    const bool v1 = (gi1 < Nc);
    // gt item: one per thread over [16][16] float4s
    const int gj  = tid >> 4;            // 0..15
    const bool gvj = (gj < NG);

    unsigned long long acc[4][8];
#pragma unroll
    for (int ii = 0; ii < 4; ii++)
#pragma unroll
        for (int jj = 0; jj < 8; jj++) acc[ii][jj] = 0ull;

    float saAcc0 = 0.f, saAcc1 = 0.f;
    int   gfound = 0;

    float4 xr0, xr1, gr;

    auto do_load = [&](int kbase) {
        xr0 = *reinterpret_cast<const float4*>(
            &phb[(size_t)gi0 * Cc * HWc + kbase + pc0]);
        if (v1)
            xr1 = *reinterpret_cast<const float4*>(
                &phb[(size_t)gi1 * Cc * HWc + kbase + pc0]);
        if (gvj)
            gr = *reinterpret_cast<const float4*>(
                &ghb[(size_t)gj * Cc * HWc + kbase + pc0]);
    };

    auto do_transform = [&](float* bw, float4 x0, float4 x1, float4 g) -> int {
        int myW = 0;
        {   // pred item 0
            float4 a4, b4o, c4;
            float* xs = &x0.x; float* as = &a4.x; float* bs = &b4o.x; float* cs = &c4.x;
#pragma unroll
            for (int qq = 0; qq < 4; qq++) {
                float xv = xs[qq];
                float e = __expf(-fabsf(xv));
                float l = __logf(1.0f + e);
                float r = __fdividef(1.0f, 1.0f + e);
                float p   = (xv >= 0.f) ? r : e * r;
                float omp = (xv >= 0.f) ? e * r : r;
                float sp   = fmaxf(xv, 0.f) + l;
                float spmx = fmaxf(-xv, 0.f) + l;
                float p2 = p * p;
                as[qq] = sp * p2;
                bs[qq] = -(xv * p2);
                cs[qq] = spmx * omp * omp;
            }
            saAcc0 += a4.x + a4.y + a4.z + a4.w;
            int so = pr0 * KIN + pc0;
            *reinterpret_cast<float4*>(&bw[OFF_A + so]) = a4;
            *reinterpret_cast<float4*>(&bw[OFF_B + so]) = b4o;
            *reinterpret_cast<float4*>(&bw[OFF_C + so]) = c4;
        }
        if (v1) {   // pred item 1
            float4 a4, b4o, c4;
            float* xs = &x1.x; float* as = &a4.x; float* bs = &b4o.x; float* cs = &c4.x;
#pragma unroll
            for (int qq = 0; qq < 4; qq++) {
                float xv = xs[qq];
                float e = __expf(-fabsf(xv));
                float l = __logf(1.0f + e);
                float r = __fdividef(1.0f, 1.0f + e);
                float p   = (xv >= 0.f) ? r : e * r;
                float omp = (xv >= 0.f) ? e * r : r;
                float sp   = fmaxf(xv, 0.f) + l;
                float spmx = fmaxf(-xv, 0.f) + l;
                float p2 = p * p;
                as[qq] = sp * p2;
                bs[qq] = -(xv * p2);
                cs[qq] = spmx * omp * omp;
            }
            saAcc1 += a4.x + a4.y + a4.z + a4.w;
            int so = pr1 * KIN + pc0;
            *reinterpret_cast<float4*>(&bw[OFF_A + so]) = a4;
            *reinterpret_cast<float4*>(&bw[OFF_B + so]) = b4o;
            *reinterpret_cast<float4*>(&bw[OFF_C + so]) = c4;
        }
        {   // gt item
            float4 u4 = {0,0,0,0}, v4 = {0,0,0,0}, w4 = {0,0,0,0};
            if (gvj) {
                float* ts = &g.x; float* us = &u4.x; float* vs = &v4.x; float* wsp = &w4.x;
#pragma unroll
                for (int qq = 0; qq < 4; qq++) {
                    float tt = ts[qq];
                    gfound |= (tt > 0.f);
                    if (tt == 1.0f) { wsp[qq] = 1.0f; myW = 1; }
                    else {
                        float o  = 1.0f - tt;
                        float o2 = o * o;
                        float u  = o2 * o2;
                        us[qq] = u; vs[qq] = tt * u;
                    }
                }
            }
            int so = gj * KIN + pc0;
            *reinterpret_cast<float4*>(&bw[OFF_U + so]) = u4;
            *reinterpret_cast<float4*>(&bw[OFF_V + so]) = v4;
            *reinterpret_cast<float4*>(&bw[OFF_W + so]) = w4;
        }
        return myW;
    };

    // ---- prologue: tile 0
    do_load(k0);
    int myW = do_transform(sm, xr0, xr1, gr);
    int hasW = __syncthreads_or(myW);

    for (int t = 0; t < NIT; ++t) {
        float* bufR = sm + (t & 1) * HALF;
        float* bufW = sm + ((t + 1) & 1) * HALF;
        const bool more = (t + 1 < NIT);

        if (more) do_load(k0 + (t + 1) * KIN);

        // ---- FMA on bufR
#pragma unroll
        for (int s = 0; s < KIN / 32; ++s) {
            const int kk = 2 * lk + 32 * s;
            unsigned long long uj[8], vj[8];
#pragma unroll
            for (int jj = 0; jj < 8; jj++) {
                int jo = (j_base + jj) * KIN + kk;
                uj[jj] = *reinterpret_cast<unsigned long long*>(&bufR[OFF_U + jo]);
                vj[jj] = *reinterpret_cast<unsigned long long*>(&bufR[OFF_V + jo]);
            }
#pragma unroll
            for (int ii = 0; ii < 4; ii++) {
                int io = (i_loc + ii) * KIN + kk;
                unsigned long long a2 =
                    *reinterpret_cast<unsigned long long*>(&bufR[OFF_A + io]);
                unsigned long long b2 =
                    *reinterpret_cast<unsigned long long*>(&bufR[OFF_B + io]);
#pragma unroll
                for (int jj = 0; jj < 8; jj++) {
                    FMA_F32X2(acc[ii][jj], a2, uj[jj], acc[ii][jj]);
                    FMA_F32X2(acc[ii][jj], b2, vj[jj], acc[ii][jj]);
                }
            }
            if (hasW) {                            // t==1 pixels: essentially never
                unsigned long long wj[8];
#pragma unroll
                for (int jj = 0; jj < 8; jj++)
                    wj[jj] = *reinterpret_cast<unsigned long long*>(
                        &bufR[OFF_W + (j_base + jj) * KIN + kk]);
#pragma unroll
                for (int ii = 0; ii < 4; ii++) {
                    int io = (i_loc + ii) * KIN + kk;
                    unsigned long long c2 =
                        *reinterpret_cast<unsigned long long*>(&bufR[OFF_C + io]);
#pragma unroll
                    for (int jj = 0; jj < 8; jj++)
                        FMA_F32X2(acc[ii][jj], c2, wj[jj], acc[ii][jj]);
                }
            }
        }

        int myW2 = 0;
        if (more) myW2 = do_transform(bufW, xr0, xr1, gr);
        hasW = __syncthreads_or(myW2);
    }

    // ---- epilogue: reductions + owned-slice stores (no atomics)
    // mask partial (identical across i-halves; ih==0 writes)
    {
        unsigned bal = __ballot_sync(0xffffffffu, gfound);
        int any = (bal >> (16 * half)) & 0xFFFF;
        int gjw = tid >> 4;
        if (ih == 0 && lk == 0 && gjw < NG)
            g_maskp[((b * NG + gjw) * Cc + c) * XB + xb] = (any != 0);
    }
    // g_sap (global rows gi0 / gi1, owned by this ih)
    {
        float v = saAcc0;
#pragma unroll
        for (int off = 8; off; off >>= 1)
            v += __shfl_xor_sync(0xffffffffu, v, off);
        if (lk == 0)
            g_sap[((b * Nc + gi0) * Cc + c) * XB + xb] = v;
        float v1r = saAcc1;
#pragma unroll
        for (int off = 8; off; off >>= 1)
            v1r += __shfl_xor_sync(0xffffffffu, v1r, off);
        if (lk == 0 && v1)
            g_sap[((b * Nc + gi1) * Cc + c) * XB + xb] = v1r;
    }
    // g_accp
#pragma unroll
    for (int ii = 0; ii < 4; ii++) {
#pragma unroll
        for (int jj = 0; jj < 8; jj++) {
            unsigned long long a = acc[ii][jj];
            float v = __uint_as_float((unsigned)(a & 0xffffffffu)) +
                      __uint_as_float((unsigned)(a >> 32));
#pragma unroll
            for (int off = 8; off; off >>= 1)
                v += __shfl_xor_sync(0xffffffffu, v, off);
            if (lk == 0) {
                int i = ih * IL + i_loc + ii, j = j_base + jj;
                if (i < Nc && j < NG)
                    g_accp[(((b * Nc + i) * NG + j) * Cc + c) * XB + xb] = v;
            }
        }
    }
}

// ---------------------------------------------------------------------------
// Kernel 2: finalize — ONE WARP per (j, i, b); grid (NG, Nc, Bc) = 1500.
// lane = channel c; all loads unconditional/independent; shuffle reduction.
// ---------------------------------------------------------------------------
__global__ __launch_bounds__(32, 32)
void finalize_kernel(const float* __restrict__ ps,
                     const float* __restrict__ po,
                     const float* __restrict__ go,
                     float* __restrict__ out) {
    const int j = blockIdx.x, i = blockIdx.y, b = blockIdx.z;
    const int lane = threadIdx.x;
    const bool valid = (lane < Cc);
    const int c = valid ? lane : 0;

    // ---- issue ALL loads up-front, independent (XB=8 -> two vec4 each)
    const int4*   mpp = reinterpret_cast<const int4*>(
        &g_maskp[((b * NG + j) * Cc + c) * XB]);
    const float4* app = reinterpret_cast<const float4*>(
        &g_accp[(((b * Nc + i) * NG + j) * Cc + c) * XB]);
    const float4* spp = reinterpret_cast<const float4*>(
        &g_sap[((b * Nc + i) * Cc + c) * XB]);
    int4   mpa = mpp[0], mpb = mpp[1];
    float4 apa = app[0], apb = app[1];
    float4 spa = spp[0], spb = spp[1];
    float  p0  = __ldg(&po[((size_t)((b * Nc + i) * Cc + c)) * 2 + 0]);
    float  p1  = __ldg(&po[((size_t)((b * Nc + i) * Cc + c)) * 2 + 1]);
    float  g0  = __ldg(&go[((size_t)((b * NG + j) * Cc + c)) * 2 + 0]);
    float  g1  = __ldg(&go[((size_t)((b * NG + j) * Cc + c)) * 2 + 1]);
    float  sv  = __ldg(&ps[b * Nc + i]);

    int   m   = valid ? (((mpa.x | mpa.y | mpa.z | mpa.w) |
                          (mpb.x | mpb.y | mpb.z | mpb.w)) != 0) : 0;
    float hmc = valid ? (apa.x + apa.y + apa.z + apa.w +
                         apb.x + apb.y + apb.z + apb.w) : 0.f;
    float sac = spa.x + spa.y + spa.z + spa.w +
                spb.x + spb.y + spb.z + spb.w;

    float s0 = __fdividef(1.0f, 1.0f + __expf(-p0));
    float s1 = __fdividef(1.0f, 1.0f + __expf(-p1));
    float d0 = s0 - g0, d1 = s1 - g1;
    float offc = (valid && m) ? (d0 * d0 + d1 * d1) : 0.f;
    float corr = (valid && !m) ? sac : 0.f;
    float kpc  = (float)m;

#pragma unroll
    for (int off = 16; off; off >>= 1) {
        hmc  += __shfl_xor_sync(0xffffffffu, hmc,  off);
        offc += __shfl_xor_sync(0xffffffffu, offc, off);
        corr += __shfl_xor_sync(0xffffffffu, corr, off);
        kpc  += __shfl_xor_sync(0xffffffffu, kpc,  off);
    }

    if (lane == 0) {
        float e = __expf(-fabsf(sv));
        float l = __logf(1.0f + e);
        float r = __fdividef(1.0f, 1.0f + e);
        float sig_neg = (sv >= 0.f) ? e * r : r;
        float sp_neg  = fmaxf(-sv, 0.f) + l;
        float score = 0.25f * sp_neg * sig_neg * sig_neg;

        float kp = fmaxf(kpc, 1.0f);
        float hm = (hmc - corr) / kp;
        out[(b * Nc + i) * NG + j] = 2.0f * hm + score + offc / kp * 0.5f;
    }
}

// ---------------------------------------------------------------------------
extern "C" void kernel_launch(void* const* d_in, const int* in_sizes, int n_in,
                              void* d_out, int out_size) {
    const float* ph = (const float*)d_in[0];
    const float* ps = (const float*)d_in[1];
    const float* po = (const float*)d_in[2];
    const float* gh = (const float*)d_in[3];
    const float* go = (const float*)d_in[4];
    float* out = (float*)d_out;

    cudaFuncSetAttribute(gemm_kernel,
                         cudaFuncAttributeMaxDynamicSharedMemorySize,
                         (int)SMEM_BYTES);

    gemm_kernel<<<dim3(XB * 2, Cc, Bc), THREADS, SMEM_BYTES>>>(ph, gh);
    finalize_kernel<<<dim3(NG, Nc, Bc), 32>>>(ps, po, go, out);
}

// round 13
// speedup vs baseline: 1.1721x; 1.1721x over previous
#include <cuda_runtime.h>
#include <cuda_bf16.h>
#include <cstdint>

// Problem constants
constexpr int Bc  = 2;
constexpr int Nc  = 50;
constexpr int NG  = 15;
constexpr int Cc  = 17;
constexpr int HWc = 4096;

constexpr int KCHUNK = 1024;
constexpr int KIN    = 64;
constexpr int NIT    = KCHUNK / KIN;   // 16
constexpr int IPAD   = 64;
constexpr int JPAD   = 16;
constexpr int THREADS = 512;
constexpr int XB     = HWc / KCHUNK;   // 4 k-blocks

// one smem buffer: A,B,C [IPAD][KIN], U,V,W [JPAD][KIN]
constexpr int OFF_A = 0;
constexpr int OFF_B = OFF_A + IPAD * KIN;
constexpr int OFF_C = OFF_B + IPAD * KIN;
constexpr int OFF_U = OFF_C + IPAD * KIN;
constexpr int OFF_V = OFF_U + JPAD * KIN;
constexpr int OFF_W = OFF_V + JPAD * KIN;
constexpr int HALF  = OFF_W + JPAD * KIN;
constexpr size_t SMEM_BYTES = 2 * HALF * sizeof(float);  // 120 KB

// Partial accumulators: each slot written by exactly one block. No init/atomics.
__device__ __align__(16) float g_accp[Bc * Nc * NG * Cc * XB];
__device__ __align__(16) float g_sap [Bc * Nc * Cc * XB];
__device__ __align__(16) int   g_maskp[Bc * NG * Cc * XB];

#define FMA_F32X2(d, a, b, c) \
    asm("fma.rn.f32x2 %0, %1, %2, %3;" : "=l"(d) : "l"(a), "l"(b), "l"(c))

// ---------------------------------------------------------------------------
// Kernel 1: fused transform + 3-term GEMM + mask partials, f32x2,
// double-buffered KIN=64.  grid (4, Cc, Bc) = 136 blocks, block 512.
// NEW warp map (crossbar-balanced): warp w: ig = w>>1 -> i rows [8ig, 8ig+8);
// jg = w&1; lanes 0-15 -> j [jg*8, jg*8+4), lanes 16-31 -> j [jg*8+4, jg*8+8).
// U/V duplication x8 (was x16), A/B x2 (was x1): 128 KB/tile vs 160 KB.
// ---------------------------------------------------------------------------
__global__ __launch_bounds__(THREADS, 1)
void gemm_kernel(const float* __restrict__ ph, const float* __restrict__ gh) {
    extern __shared__ float sm[];

    const int xb = blockIdx.x, c = blockIdx.y, b = blockIdx.z;
    const int k0 = xb * KCHUNK;

    const int tid  = threadIdx.x;
    const int lane = tid & 31;
    const int wrp  = tid >> 5;
    const int lk   = lane & 15;
    const int half = lane >> 4;
    const int ig   = wrp >> 1;           // 0..7
    const int jg   = wrp & 1;            // 0..1
    const int i_base = ig * 8;
    const int j_base = jg * 8 + half * 4;

    // zero pad rows [Nc, IPAD) in BOTH buffers once
    for (int idx = tid; idx < (IPAD - Nc) * KIN; idx += THREADS) {
#pragma unroll
        for (int bu = 0; bu < 2; bu++) {
            sm[bu * HALF + OFF_A + Nc * KIN + idx] = 0.f;
            sm[bu * HALF + OFF_B + Nc * KIN + idx] = 0.f;
            sm[bu * HALF + OFF_C + Nc * KIN + idx] = 0.f;
        }
    }

    const float* phb = ph + ((size_t)(b * Nc * Cc + c)) * HWc;
    const float* ghb = gh + ((size_t)(b * NG * Cc + c)) * HWc;

    const int pr0 = tid >> 4;                 // q=0 pred row (0..31)
    const int pc0 = (tid & 15) << 2;
    const int pr1 = (tid + THREADS) >> 4;     // q=1 pred row (32..63)
    const bool q1v = (tid < (Nc * (KIN / 4) - THREADS));  // tid < 288
    const int gj   = tid >> 4;                // gt row
    const bool gv  = (tid < JPAD * (KIN / 4));            // tid < 256

    unsigned long long acc[8][4];
#pragma unroll
    for (int ii = 0; ii < 8; ii++)
#pragma unroll
        for (int jj = 0; jj < 4; jj++) acc[ii][jj] = 0ull;

    float saAcc0 = 0.f, saAcc1 = 0.f;   // per-thread Sum_k A (for g_sap)
    int   gfound = 0;                   // any gt>0 in this thread's slice

    float4 xr0, xr1, gr;

    auto do_transform = [&](float* bw, float4 x0, float4 x1, float4 g) -> int {
        int myW = 0;
        {
            float4 a4, b4o, c4;
            float* xs = &x0.x; float* as = &a4.x; float* bs = &b4o.x; float* cs = &c4.x;
#pragma unroll
            for (int qq = 0; qq < 4; qq++) {
                float x = xs[qq];
                float e = __expf(-fabsf(x));
                float l = __logf(1.0f + e);
                float r = __fdividef(1.0f, 1.0f + e);
                float p   = (x >= 0.f) ? r : e * r;
                float omp = (x >= 0.f) ? e * r : r;
                float sp   = fmaxf(x, 0.f) + l;
                float spmx = fmaxf(-x, 0.f) + l;
                float p2 = p * p;
                as[qq] = sp * p2;
                bs[qq] = -(x * p2);
                cs[qq] = spmx * omp * omp;
            }
            saAcc0 += a4.x + a4.y + a4.z + a4.w;
            int so = pr0 * KIN + pc0;
            *reinterpret_cast<float4*>(&bw[OFF_A + so]) = a4;
            *reinterpret_cast<float4*>(&bw[OFF_B + so]) = b4o;
            *reinterpret_cast<float4*>(&bw[OFF_C + so]) = c4;
        }
        if (q1v) {
            float4 a4, b4o, c4;
            float* xs = &x1.x; float* as = &a4.x; float* bs = &b4o.x; float* cs = &c4.x;
#pragma unroll
            for (int qq = 0; qq < 4; qq++) {
                float x = xs[qq];
                float e = __expf(-fabsf(x));
                float l = __logf(1.0f + e);
                float r = __fdividef(1.0f, 1.0f + e);
                float p   = (x >= 0.f) ? r : e * r;
                float omp = (x >= 0.f) ? e * r : r;
                float sp   = fmaxf(x, 0.f) + l;
                float spmx = fmaxf(-x, 0.f) + l;
                float p2 = p * p;
                as[qq] = sp * p2;
                bs[qq] = -(x * p2);
                cs[qq] = spmx * omp * omp;
            }
            saAcc1 += a4.x + a4.y + a4.z + a4.w;
            int so = pr1 * KIN + pc0;
            *reinterpret_cast<float4*>(&bw[OFF_A + so]) = a4;
            *reinterpret_cast<float4*>(&bw[OFF_B + so]) = b4o;
            *reinterpret_cast<float4*>(&bw[OFF_C + so]) = c4;
        }
        if (gv) {
            float4 u4 = {0,0,0,0}, v4 = {0,0,0,0}, w4 = {0,0,0,0};
            if (gj < NG) {
                float* ts = &g.x; float* us = &u4.x; float* vs = &v4.x; float* wsp = &w4.x;
#pragma unroll
                for (int qq = 0; qq < 4; qq++) {
                    float tt = ts[qq];
                    gfound |= (tt > 0.f);
                    if (tt == 1.0f) { wsp[qq] = 1.0f; myW = 1; }
                    else {
                        float o  = 1.0f - tt;
                        float o2 = o * o;
                        float u  = o2 * o2;
                        us[qq] = u; vs[qq] = tt * u;
                    }
                }
            }
            int so = gj * KIN + pc0;
            *reinterpret_cast<float4*>(&bw[OFF_U + so]) = u4;
            *reinterpret_cast<float4*>(&bw[OFF_V + so]) = v4;
            *reinterpret_cast<float4*>(&bw[OFF_W + so]) = w4;
        }
        return myW;
    };

    auto do_load = [&](int kbase) {
        xr0 = *reinterpret_cast<const float4*>(
            &phb[(size_t)pr0 * Cc * HWc + kbase + pc0]);
        if (q1v)
            xr1 = *reinterpret_cast<const float4*>(
                &phb[(size_t)pr1 * Cc * HWc + kbase + pc0]);
        if (gv && gj < NG)
            gr = *reinterpret_cast<const float4*>(
                &ghb[(size_t)gj * Cc * HWc + kbase + pc0]);
    };

    // ---- prologue: tile 0
    do_load(k0);
    int myW = do_transform(sm, xr0, xr1, gr);
    int hasW = __syncthreads_or(myW);

    for (int t = 0; t < NIT; ++t) {
        float* bufR = sm + (t & 1) * HALF;
        float* bufW = sm + ((t + 1) & 1) * HALF;
        const bool more = (t + 1 < NIT);

        if (more) do_load(k0 + (t + 1) * KIN);

        // ---- FMA on bufR: 8 i x 4 j per (warp, half)
#pragma unroll
        for (int s = 0; s < KIN / 32; ++s) {
            const int kk = 2 * lk + 32 * s;
            unsigned long long uj[4], vj[4];
#pragma unroll
            for (int jj = 0; jj < 4; jj++) {
                int jo = (j_base + jj) * KIN + kk;
                uj[jj] = *reinterpret_cast<unsigned long long*>(&bufR[OFF_U + jo]);
                vj[jj] = *reinterpret_cast<unsigned long long*>(&bufR[OFF_V + jo]);
            }
#pragma unroll
            for (int ii = 0; ii < 8; ii++) {
                int io = (i_base + ii) * KIN + kk;
                unsigned long long a2 =
                    *reinterpret_cast<unsigned long long*>(&bufR[OFF_A + io]);
                unsigned long long b2 =
                    *reinterpret_cast<unsigned long long*>(&bufR[OFF_B + io]);
#pragma unroll
                for (int jj = 0; jj < 4; jj++) {
                    FMA_F32X2(acc[ii][jj], a2, uj[jj], acc[ii][jj]);
                    FMA_F32X2(acc[ii][jj], b2, vj[jj], acc[ii][jj]);
                }
            }
            if (hasW) {                            // t==1 pixels: essentially never
                unsigned long long wj[4];
#pragma unroll
                for (int jj = 0; jj < 4; jj++)
                    wj[jj] = *reinterpret_cast<unsigned long long*>(
                        &bufR[OFF_W + (j_base + jj) * KIN + kk]);
#pragma unroll
                for (int ii = 0; ii < 8; ii++) {
                    int io = (i_base + ii) * KIN + kk;
                    unsigned long long c2 =
                        *reinterpret_cast<unsigned long long*>(&bufR[OFF_C + io]);
#pragma unroll
                    for (int jj = 0; jj < 4; jj++)
                        FMA_F32X2(acc[ii][jj], c2, wj[jj], acc[ii][jj]);
                }
            }
        }

        int myW2 = 0;
        if (more) myW2 = do_transform(bufW, xr0, xr1, gr);
        hasW = __syncthreads_or(myW2);
    }

    // ---- epilogue: reductions + owned-slice stores (no atomics)
    // mask partial: any gt>0 per (gj) over this k-chunk
    {
        unsigned bal = __ballot_sync(0xffffffffu, gfound);
        int any = (bal >> (16 * half)) & 0xFFFF;
        if (lk == 0 && gj < NG)
            g_maskp[((b * NG + gj) * Cc + c) * XB + xb] = (any != 0);
    }
    // g_sap
    {
        float v = saAcc0;
#pragma unroll
        for (int off = 8; off; off >>= 1)
            v += __shfl_xor_sync(0xffffffffu, v, off);
        if (lk == 0)
            g_sap[((b * Nc + pr0) * Cc + c) * XB + xb] = v;
        if (wrp < 9) {               // q=1 rows 32..49 live in warps 0..8
            float v1 = saAcc1;
#pragma unroll
            for (int off = 8; off; off >>= 1)
                v1 += __shfl_xor_sync(0xffffffffu, v1, off);
            if (lk == 0)
                g_sap[((b * Nc + pr1) * Cc + c) * XB + xb] = v1;
        }
    }
    // g_accp: i covered by ONE warp each (ig unique), j by (jg,half) -> no overlap
#pragma unroll
    for (int ii = 0; ii < 8; ii++) {
#pragma unroll
        for (int jj = 0; jj < 4; jj++) {
            unsigned long long a = acc[ii][jj];
            float v = __uint_as_float((unsigned)(a & 0xffffffffu)) +
                      __uint_as_float((unsigned)(a >> 32));
#pragma unroll
            for (int off = 8; off; off >>= 1)
                v += __shfl_xor_sync(0xffffffffu, v, off);
            if (lk == 0) {
                int i = i_base + ii, j = j_base + jj;
                if (i < Nc && j < NG)
                    g_accp[(((b * Nc + i) * NG + j) * Cc + c) * XB + xb] = v;
            }
        }
    }
}

// ---------------------------------------------------------------------------
// Kernel 2: finalize — ONE WARP per (j, i, b); grid (NG, Nc, Bc) = 1500.
// ---------------------------------------------------------------------------
__global__ __launch_bounds__(32, 32)
void finalize_kernel(const float* __restrict__ ps,
                     const float* __restrict__ po,
                     const float* __restrict__ go,
                     float* __restrict__ out) {
    const int j = blockIdx.x, i = blockIdx.y, b = blockIdx.z;
    const int lane = threadIdx.x;
    const bool valid = (lane < Cc);
    const int c = valid ? lane : 0;

    int4   mp  = *reinterpret_cast<const int4*>(
        &g_maskp[((b * NG + j) * Cc + c) * XB]);
    float4 ap  = *reinterpret_cast<const float4*>(
        &g_accp[(((b * Nc + i) * NG + j) * Cc + c) * XB]);
    float4 sp4 = *reinterpret_cast<const float4*>(
        &g_sap[((b * Nc + i) * Cc + c) * XB]);
    float  p0  = __ldg(&po[((size_t)((b * Nc + i) * Cc + c)) * 2 + 0]);
    float  p1  = __ldg(&po[((size_t)((b * Nc + i) * Cc + c)) * 2 + 1]);
    float  g0  = __ldg(&go[((size_t)((b * NG + j) * Cc + c)) * 2 + 0]);
    float  g1  = __ldg(&go[((size_t)((b * NG + j) * Cc + c)) * 2 + 1]);
    float  sv  = __ldg(&ps[b * Nc + i]);

    int   m   = valid ? ((mp.x | mp.y | mp.z | mp.w) != 0) : 0;
    float hmc = valid ? (ap.x + ap.y + ap.z + ap.w) : 0.f;
    float sac = sp4.x + sp4.y + sp4.z + sp4.w;

    float s0 = __fdividef(1.0f, 1.0f + __expf(-p0));
    float s1 = __fdividef(1.0f, 1.0f + __expf(-p1));
    float d0 = s0 - g0, d1 = s1 - g1;
    float offc = (valid && m) ? (d0 * d0 + d1 * d1) : 0.f;
    float corr = (valid && !m) ? sac : 0.f;
    float kpc  = (float)m;

#pragma unroll
    for (int off = 16; off; off >>= 1) {
        hmc  += __shfl_xor_sync(0xffffffffu, hmc,  off);
        offc += __shfl_xor_sync(0xffffffffu, offc, off);
        corr += __shfl_xor_sync(0xffffffffu, corr, off);
        kpc  += __shfl_xor_sync(0xffffffffu, kpc,  off);
    }

    if (lane == 0) {
        float e = __expf(-fabsf(sv));
        float l = __logf(1.0f + e);
        float r = __fdividef(1.0f, 1.0f + e);
        float sig_neg = (sv >= 0.f) ? e * r : r;
        float sp_neg  = fmaxf(-sv, 0.f) + l;
        float score = 0.25f * sp_neg * sig_neg * sig_neg;

        float kp = fmaxf(kpc, 1.0f);
        float hm = (hmc - corr) / kp;
        out[(b * Nc + i) * NG + j] = 2.0f * hm + score + offc / kp * 0.5f;
    }
}

// ---------------------------------------------------------------------------
extern "C" void kernel_launch(void* const* d_in, const int* in_sizes, int n_in,
                              void* d_out, int out_size) {
    const float* ph = (const float*)d_in[0];
    const float* ps = (const float*)d_in[1];
    const float* po = (const float*)d_in[2];
    const float* gh = (const float*)d_in[3];
    const float* go = (const float*)d_in[4];
    float* out = (float*)d_out;

    cudaFuncSetAttribute(gemm_kernel,
                         cudaFuncAttributeMaxDynamicSharedMemorySize,
                         (int)SMEM_BYTES);

    gemm_kernel<<<dim3(XB, Cc, Bc), THREADS, SMEM_BYTES>>>(ph, gh);
    finalize_kernel<<<dim3(NG, Nc, Bc), 32>>>(ps, po, go, out);
}